// round 12
// baseline (speedup 1.0000x reference)
#include <cuda_runtime.h>
#include <cuda_bf16.h>
#include <cuda_fp16.h>
#include <cstdint>

#define NE 50000
#define NP 25000
#define EN 200000
#define D  128
#define NTOT (NE + NP)
#define BINS (2 * NE + 2 * NP)
#define CAP 64
#define BLK_E ((NE + 127) / 128)       // 391
#define BLK_P ((NP + 127) / 128)       // 196

// ---------------- device scratch ----------------
__device__ float g_xeF[NE * D];
__device__ float g_xpF[NP * D];
__device__ uint32_t g_hs[(2 * NE + 2 * NP) * (D / 2)];   // half2-packed hs rows
__device__ float g_es[4 * NE];
__device__ float g_edA[NTOT];
__device__ float g_edB[NTOT];
__device__ float g_vd[12 * D];
__device__ float g_colsum[D];
__device__ int   g_deg[BINS];
__device__ int   g_csr_src[BINS * CAP];

// MMA fragment arrays (hi/lo bf16 split), fragment-permuted layout
__device__ uint4 g_xeh[BLK_E * 2048];
__device__ uint4 g_xel[BLK_E * 2048];
__device__ uint4 g_xph[BLK_P * 2048];
__device__ uint4 g_xpl[BLK_P * 2048];
__device__ uint2 g_wh[12 * 16 * 8 * 32];
__device__ uint2 g_wl[12 * 16 * 8 * 32];

struct EPtr { const int* src[4]; const int* dst[4]; };

__device__ __forceinline__ size_t hs_off_u(int t) {
    return (t < 2) ? (size_t)t * NE * (D / 2)
                   : (size_t)2 * NE * (D / 2) + (size_t)(t - 2) * NP * (D / 2);
}
__device__ __forceinline__ int bin_base(int t) {
    const int b[4] = {0, NE, NE + NP, NE + 2 * NP};
    return b[t];
}
__device__ __forceinline__ uint32_t pack_bf16(__nv_bfloat16 a, __nv_bfloat16 b) {
    return (uint32_t)__bfloat16_as_ushort(a) | ((uint32_t)__bfloat16_as_ushort(b) << 16);
}

// ---------------- CSR build + vd (all layers) ----------------
__global__ void k_zero_int(int* p, int n) {
    int i = blockIdx.x * blockDim.x + threadIdx.x;
    if (i < n) p[i] = 0;
}

#define SCAT_B ((4 * EN + 255) / 256)    // 3125
#define VD_B   ((12 * 128 * 32) / 256)   // 192

__global__ void k_scatter(EPtr ep, const float* __restrict__ Wd_all,
                          const float* __restrict__ ad_all) {
    if (blockIdx.x == 0 && threadIdx.x < D) g_colsum[threadIdx.x] = 0.f;
    int b = blockIdx.x;
    int tid = threadIdx.x;
    if (b < SCAT_B) {
        int idx = b * 256 + tid;
        if (idx >= 4 * EN) return;
        int t = idx / EN, e = idx - t * EN;
        int bin = bin_base(t) + ep.dst[t][e];
        int pos = atomicAdd(&g_deg[bin], 1);
        if (pos < CAP) g_csr_src[bin * CAP + pos] = ep.src[t][e];
    } else {
        int gw = ((b - SCAT_B) * 256 + tid) >> 5;
        int lane = tid & 31;
        if (gw >= 12 * 128) return;
        int lt = gw >> 7, r = gw & 127;
        float4 w = ((const float4*)(Wd_all + (size_t)(lt * D + r) * D))[lane];
        float4 a = ((const float4*)(ad_all + (size_t)lt * D))[lane];
        float p = w.x * a.x + w.y * a.y + w.z * a.z + w.w * a.w;
#pragma unroll
        for (int o = 16; o > 0; o >>= 1) p += __shfl_down_sync(0xffffffffu, p, o);
        if (lane == 0) g_vd[lt * D + r] = p;
    }
}

// ---------------- one-time setup ----------------
__device__ __forceinline__ void convert_x_body(const float* __restrict__ x, int M,
                                               uint4* __restrict__ fh, uint4* __restrict__ fl,
                                               int f) {
    int tile = f >> 11, rem = f & 2047;
    int m = rem >> 8, ks = (rem >> 5) & 7, lane = rem & 31;
    int g = lane >> 2, tg = lane & 3;
    int r0 = tile * 128 + m * 16 + g;
    int r1 = r0 + 8;
    int c0 = ks * 16 + tg * 2;
    int c1 = c0 + 8;

    float2 v00 = (r0 < M) ? *(const float2*)(x + (size_t)r0 * D + c0) : make_float2(0.f, 0.f);
    float2 v01 = (r0 < M) ? *(const float2*)(x + (size_t)r0 * D + c1) : make_float2(0.f, 0.f);
    float2 v10 = (r1 < M) ? *(const float2*)(x + (size_t)r1 * D + c0) : make_float2(0.f, 0.f);
    float2 v11 = (r1 < M) ? *(const float2*)(x + (size_t)r1 * D + c1) : make_float2(0.f, 0.f);

    uint4 H, L;
    __nv_bfloat16 h, h2;

    h = __float2bfloat16(v00.x); h2 = __float2bfloat16(v00.y);
    H.x = pack_bf16(h, h2);
    L.x = pack_bf16(__float2bfloat16(v00.x - __bfloat162float(h)),
                    __float2bfloat16(v00.y - __bfloat162float(h2)));
    h = __float2bfloat16(v10.x); h2 = __float2bfloat16(v10.y);
    H.y = pack_bf16(h, h2);
    L.y = pack_bf16(__float2bfloat16(v10.x - __bfloat162float(h)),
                    __float2bfloat16(v10.y - __bfloat162float(h2)));
    h = __float2bfloat16(v01.x); h2 = __float2bfloat16(v01.y);
    H.z = pack_bf16(h, h2);
    L.z = pack_bf16(__float2bfloat16(v01.x - __bfloat162float(h)),
                    __float2bfloat16(v01.y - __bfloat162float(h2)));
    h = __float2bfloat16(v11.x); h2 = __float2bfloat16(v11.y);
    H.w = pack_bf16(h, h2);
    L.w = pack_bf16(__float2bfloat16(v11.x - __bfloat162float(h)),
                    __float2bfloat16(v11.y - __bfloat162float(h2)));

    fh[f] = H;
    fl[f] = L;
}

#define SETUP_BW 192
#define SETUP_BE (BLK_E * 2048 / 256)
#define SETUP_BP (BLK_P * 2048 / 256)
#define SETUP_BED ((NTOT * 32 + 255) / 256)

__global__ void k_setup(const float* __restrict__ xe, const float* __restrict__ xp,
                        const float* __restrict__ Ws_all) {
    int b = blockIdx.x;
    int tid = threadIdx.x;
    if (b < SETUP_BW) {
        int idx = b * 256 + tid;
        int lt = idx >> 12, nb = (idx >> 8) & 15, ks = (idx >> 5) & 7, lane = idx & 31;
        int g = lane >> 2, tg = lane & 3;
        int n = nb * 8 + g;
        int k0 = ks * 16 + tg * 2;
        const float* W = Ws_all + (size_t)lt * D * D;
        float f0 = W[(size_t)k0 * D + n];
        float f1 = W[(size_t)(k0 + 1) * D + n];
        float f2 = W[(size_t)(k0 + 8) * D + n];
        float f3 = W[(size_t)(k0 + 9) * D + n];
        __nv_bfloat16 h0 = __float2bfloat16(f0), h1 = __float2bfloat16(f1);
        __nv_bfloat16 h2 = __float2bfloat16(f2), h3 = __float2bfloat16(f3);
        uint2 H, L;
        H.x = pack_bf16(h0, h1);
        H.y = pack_bf16(h2, h3);
        L.x = pack_bf16(__float2bfloat16(f0 - __bfloat162float(h0)),
                        __float2bfloat16(f1 - __bfloat162float(h1)));
        L.y = pack_bf16(__float2bfloat16(f2 - __bfloat162float(h2)),
                        __float2bfloat16(f3 - __bfloat162float(h3)));
        g_wh[idx] = H;
        g_wl[idx] = L;
    } else if (b < SETUP_BW + SETUP_BE) {
        convert_x_body(xe, NE, g_xeh, g_xel, (b - SETUP_BW) * 256 + tid);
    } else if (b < SETUP_BW + SETUP_BE + SETUP_BP) {
        convert_x_body(xp, NP, g_xph, g_xpl, (b - SETUP_BW - SETUP_BE) * 256 + tid);
    } else {
        int gw = ((b - SETUP_BW - SETUP_BE - SETUP_BP) * 256 + tid) >> 5;
        int lane = tid & 31;
        if (gw >= NTOT) return;
        bool elem = gw < NE;
        int d = elem ? gw : gw - NE;
        const float* x = elem ? xe : xp;
        int tA = elem ? 0 : 1, tB = elem ? 3 : 2;
        float4 xr = ((const float4*)(x + (size_t)d * D))[lane];
        float4 vA = ((const float4*)(g_vd + tA * D))[lane];
        float4 vB = ((const float4*)(g_vd + tB * D))[lane];
        float eA = xr.x * vA.x + xr.y * vA.y + xr.z * vA.z + xr.w * vA.w;
        float eB = xr.x * vB.x + xr.y * vB.y + xr.z * vB.z + xr.w * vB.w;
#pragma unroll
        for (int o = 16; o > 0; o >>= 1) {
            eA += __shfl_xor_sync(0xffffffffu, eA, o);
            eB += __shfl_xor_sync(0xffffffffu, eB, o);
        }
        if (lane == 0) { g_edA[gw] = eA; g_edB[gw] = eB; }
    }
}

// ---------------- split-bf16 MMA GEMM, product-major reordered ----------------
__device__ __forceinline__ void mma_bf16(float* c, const uint4& a, const uint2& b) {
    asm volatile(
        "mma.sync.aligned.m16n8k16.row.col.f32.bf16.bf16.f32 "
        "{%0,%1,%2,%3}, {%4,%5,%6,%7}, {%8,%9}, {%0,%1,%2,%3};"
        : "+f"(c[0]), "+f"(c[1]), "+f"(c[2]), "+f"(c[3])
        : "r"(a.x), "r"(a.y), "r"(a.z), "r"(a.w), "r"(b.x), "r"(b.y));
}
__device__ __forceinline__ uint32_t f2h2(float a, float b) {
    __half2 h = __floats2half2_rn(a, b);
    return *reinterpret_cast<uint32_t*>(&h);
}

__global__ __launch_bounds__(256, 2) void k_gemm_es_mma(const float* __restrict__ asrc,
                                                        int layer) {
    __shared__ float esb[128];

    int bx = blockIdx.x;
    int t, bb;
    if (bx < BLK_E)                   { t = 0; bb = bx; }
    else if (bx < 2 * BLK_E)          { t = 1; bb = bx - BLK_E; }
    else if (bx < 2 * BLK_E + BLK_P)  { t = 2; bb = bx - 2 * BLK_E; }
    else                              { t = 3; bb = bx - 2 * BLK_E - BLK_P; }

    const uint4* Ah = (t < 2) ? g_xeh : g_xph;
    const uint4* Al = (t < 2) ? g_xel : g_xpl;
    int M          = (t < 2) ? NE : NP;
    uint32_t* C    = g_hs + hs_off_u(t);
    float* es      = g_es + t * NE;
    const float* as_ = asrc + t * D;

    int tid  = threadIdx.x;
    int lane = tid & 31;
    int wid  = tid >> 5;
    int wm   = wid & 3;
    int wn   = wid >> 2;
    int row0 = bb * 128;

    if (tid < 128) esb[tid] = 0.f;
    __syncthreads();

    float acc[2][8][4];
#pragma unroll
    for (int i = 0; i < 2; i++)
#pragma unroll
        for (int j = 0; j < 8; j++)
#pragma unroll
            for (int q = 0; q < 4; q++) acc[i][j][q] = 0.f;

    size_t aBase0 = ((size_t)(bb * 8 + wm * 2 + 0) * 8) * 32 + lane;
    size_t aBase1 = ((size_t)(bb * 8 + wm * 2 + 1) * 8) * 32 + lane;
    size_t bBase  = ((size_t)((layer * 4 + t) * 16 + wn * 8) * 8) * 32 + lane;

#pragma unroll
    for (int ks = 0; ks < 8; ks++) {
        uint4 ah0 = Ah[aBase0 + (size_t)ks * 32];
        uint4 ah1 = Ah[aBase1 + (size_t)ks * 32];
        uint4 al0 = Al[aBase0 + (size_t)ks * 32];
        uint4 al1 = Al[aBase1 + (size_t)ks * 32];
        // process n-blocks in two groups of 4; within each group, product-major
        // ordering gives RAW reuse distance of 8 MMAs on each accumulator.
#pragma unroll
        for (int jb = 0; jb < 2; jb++) {
            uint2 bh[4], bl[4];
#pragma unroll
            for (int jj = 0; jj < 4; jj++) {
                int j = jb * 4 + jj;
                bh[jj] = g_wh[bBase + ((size_t)j * 8 + ks) * 32];
                bl[jj] = g_wl[bBase + ((size_t)j * 8 + ks) * 32];
            }
            // pass 1: Ah * Bh
#pragma unroll
            for (int jj = 0; jj < 4; jj++) {
                mma_bf16(acc[0][jb * 4 + jj], ah0, bh[jj]);
                mma_bf16(acc[1][jb * 4 + jj], ah1, bh[jj]);
            }
            // pass 2: Ah * Bl
#pragma unroll
            for (int jj = 0; jj < 4; jj++) {
                mma_bf16(acc[0][jb * 4 + jj], ah0, bl[jj]);
                mma_bf16(acc[1][jb * 4 + jj], ah1, bl[jj]);
            }
            // pass 3: Al * Bh
#pragma unroll
            for (int jj = 0; jj < 4; jj++) {
                mma_bf16(acc[0][jb * 4 + jj], al0, bh[jj]);
                mma_bf16(acc[1][jb * 4 + jj], al1, bh[jj]);
            }
        }
    }

    int g = lane >> 2, tg = lane & 3;
#pragma unroll
    for (int i = 0; i < 2; i++) {
        int rbase = row0 + (wm * 2 + i) * 16;
        int ra = rbase + g;
        int rb = rbase + g + 8;
        float ea = 0.f, eb = 0.f;
#pragma unroll
        for (int j = 0; j < 8; j++) {
            int col = (wn * 8 + j) * 8 + tg * 2;
            float a0 = __ldg(as_ + col), a1 = __ldg(as_ + col + 1);
            ea += acc[i][j][0] * a0 + acc[i][j][1] * a1;
            eb += acc[i][j][2] * a0 + acc[i][j][3] * a1;
            if (ra < M) C[(size_t)ra * (D / 2) + (col >> 1)] = f2h2(acc[i][j][0], acc[i][j][1]);
            if (rb < M) C[(size_t)rb * (D / 2) + (col >> 1)] = f2h2(acc[i][j][2], acc[i][j][3]);
        }
        ea += __shfl_xor_sync(0xffffffffu, ea, 1);
        ea += __shfl_xor_sync(0xffffffffu, ea, 2);
        eb += __shfl_xor_sync(0xffffffffu, eb, 1);
        eb += __shfl_xor_sync(0xffffffffu, eb, 2);
        if (tg == 0) {
            atomicAdd(&esb[(wm * 2 + i) * 16 + g], ea);
            atomicAdd(&esb[(wm * 2 + i) * 16 + 8 + g], eb);
        }
    }
    __syncthreads();
    if (tid < 128 && row0 + tid < M) es[row0 + tid] = esb[tid];
}

// ---------------- fused per-dst aggregation + frag conversion + next-layer ed ----------------
__device__ __forceinline__ void gat_accum(int t, int d, float ed, int lane,
                                          float4& acc, float& den) {
    int bin = bin_base(t) + d;
    int deg = g_deg[bin];
    if (deg == 0) return;
    int start = bin * CAP;
    int end = start + deg;

    const float* es_t = g_es + t * NE;
    const uint32_t* hs_t = g_hs + hs_off_u(t);

    int s0 = g_csr_src[start];
    float ev0 = es_t[s0];
    uint2 u0 = ((const uint2*)(hs_t + (size_t)s0 * (D / 2)))[lane];

    for (int e = start; e < end; e++) {
        float ev = ev0;
        uint2 u = u0;
        if (e + 1 < end) {
            int s1 = g_csr_src[e + 1];
            ev0 = es_t[s1];
            u0 = ((const uint2*)(hs_t + (size_t)s1 * (D / 2)))[lane];
        }
        float w = __expf(fmaxf(ev + ed, 0.f));
        den += w;
        float2 f01 = __half22float2(*reinterpret_cast<__half2*>(&u.x));
        float2 f23 = __half22float2(*reinterpret_cast<__half2*>(&u.y));
        acc.x += w * f01.x; acc.y += w * f01.y;
        acc.z += w * f23.x; acc.w += w * f23.y;
    }
}

__global__ __launch_bounds__(256) void k_agg(const float* __restrict__ bias, int layer) {
    int gw = (blockIdx.x * blockDim.x + threadIdx.x) >> 5;
    int lane = threadIdx.x & 31;
    if (gw >= NTOT) return;

    bool elem = gw < NE;
    int tA, tB, d;
    const float *b1, *b2;
    if (elem) { tA = 0; tB = 3; d = gw;       b1 = bias;     b2 = bias + 3 * D; }
    else      { tA = 1; tB = 2; d = gw - NE;  b1 = bias + D; b2 = bias + 2 * D; }

    float edA = g_edA[gw];
    float edB = g_edB[gw];

    float4 accA = {0.f, 0.f, 0.f, 0.f}, accB = {0.f, 0.f, 0.f, 0.f};
    float denA = 0.f, denB = 0.f;
    gat_accum(tA, d, edA, lane, accA, denA);
    gat_accum(tB, d, edB, lane, accB, denB);

    float ia = 1.f / fmaxf(denA, 1e-16f);
    float ib = 1.f / fmaxf(denB, 1e-16f);
    float4 bb1 = ((const float4*)b1)[lane];
    float4 bb2 = ((const float4*)b2)[lane];
    float4 o;
    o.x = bb1.x + bb2.x + accA.x * ia + accB.x * ib;
    o.y = bb1.y + bb2.y + accA.y * ia + accB.y * ib;
    o.z = bb1.z + bb2.z + accA.z * ia + accB.z * ib;
    o.w = bb1.w + bb2.w + accA.w * ia + accB.w * ib;

    if (layer == 2) {
        float* xout = elem ? g_xeF : g_xpF;
        ((float4*)(xout + (size_t)d * D))[lane] = o;
        return;
    }

    // fused frag conversion: scatter o into MMA fragment layout
    uint32_t* FH = elem ? (uint32_t*)g_xeh : (uint32_t*)g_xph;
    uint32_t* FL = elem ? (uint32_t*)g_xel : (uint32_t*)g_xpl;
    int tile = d >> 7, w128 = d & 127;
    int m = w128 >> 4, r16 = w128 & 15;
    int gsel = r16 & 7, hsel = r16 >> 3;
    size_t fbase = ((size_t)(tile * 8 + m) * 8) * 32 + gsel * 4;
    float v[4] = {o.x, o.y, o.z, o.w};
#pragma unroll
    for (int pp = 0; pp < 2; pp++) {
        int p = 2 * lane + pp;
        int ks = p >> 3, rem = p & 7;
        int tg = rem & 3, chal = rem >> 2;
        int q = chal * 2 + hsel;
        size_t addr = (fbase + (size_t)ks * 32 + tg) * 4 + q;
        float v0 = v[2 * pp], v1 = v[2 * pp + 1];
        __nv_bfloat16 h0 = __float2bfloat16(v0), h1 = __float2bfloat16(v1);
        FH[addr] = pack_bf16(h0, h1);
        FL[addr] = pack_bf16(__float2bfloat16(v0 - __bfloat162float(h0)),
                             __float2bfloat16(v1 - __bfloat162float(h1)));
    }

    // next-layer ed from o
    int nl = layer + 1;
    int ntA = elem ? 0 : 1, ntB = elem ? 3 : 2;
    float4 vA = ((const float4*)(g_vd + (nl * 4 + ntA) * D))[lane];
    float4 vB = ((const float4*)(g_vd + (nl * 4 + ntB) * D))[lane];
    float eA = o.x * vA.x + o.y * vA.y + o.z * vA.z + o.w * vA.w;
    float eB = o.x * vB.x + o.y * vB.y + o.z * vB.z + o.w * vB.w;
#pragma unroll
    for (int off = 16; off > 0; off >>= 1) {
        eA += __shfl_xor_sync(0xffffffffu, eA, off);
        eB += __shfl_xor_sync(0xffffffffu, eB, off);
    }
    if (lane == 0) { g_edA[gw] = eA; g_edB[gw] = eB; }
}

// ---------------- final reduction ----------------
#define CSB_E ((NE + 63) / 64)
#define CSB_P ((NP + 63) / 64)

__global__ void k_colsum2() {
    int c = threadIdx.x;
    int b = blockIdx.x;
    const float* x;
    int n, row0;
    if (b < CSB_E) { x = g_xeF; n = NE; row0 = b * 64; }
    else           { x = g_xpF; n = NP; row0 = (b - CSB_E) * 64; }
    float s = 0.f;
#pragma unroll 4
    for (int r = 0; r < 64; r++) {
        int row = row0 + r;
        if (row < n) s += x[(size_t)row * D + c];
    }
    atomicAdd(g_colsum + c, s);
}

__global__ void k_finalize(const float* __restrict__ lin_W, const float* __restrict__ lin_b,
                           float* __restrict__ out) {
    if (threadIdx.x == 0) {
        float o0 = lin_b[0], o1 = lin_b[1];
        const float inv = 1.f / (float)NTOT;
        for (int i = 0; i < D; i++) {
            float mv = g_colsum[i] * inv;
            o0 += mv * lin_W[2 * i];
            o1 += mv * lin_W[2 * i + 1];
        }
        out[0] = o0;
        out[1] = o1;
    }
}

// ---------------- host orchestration ----------------
extern "C" void kernel_launch(void* const* d_in, const int* in_sizes, int n_in,
                              void* d_out, int out_size) {
    const float* x_elem  = (const float*)d_in[0];
    const float* x_proc  = (const float*)d_in[1];
    const float* W_src   = (const float*)d_in[2];
    const float* W_dst   = (const float*)d_in[3];
    const float* att_src = (const float*)d_in[4];
    const float* att_dst = (const float*)d_in[5];
    const float* bias    = (const float*)d_in[6];
    const float* lin_W   = (const float*)d_in[7];
    const float* lin_b   = (const float*)d_in[8];
    EPtr ep;
    ep.src[0] = (const int*)d_in[9];  ep.dst[0] = (const int*)d_in[10];
    ep.src[1] = (const int*)d_in[11]; ep.dst[1] = (const int*)d_in[12];
    ep.src[2] = (const int*)d_in[13]; ep.dst[2] = (const int*)d_in[14];
    ep.src[3] = (const int*)d_in[15]; ep.dst[3] = (const int*)d_in[16];
    float* out = (float*)d_out;

    int* deg;
    cudaGetSymbolAddress((void**)&deg, g_deg);

    // CSR build + all-layer vd
    k_zero_int<<<(BINS + 255) / 256, 256>>>(deg, BINS);
    k_scatter<<<SCAT_B + VD_B, 256>>>(ep, W_dst, att_dst);

    // one-time: all W frags, input x frags, layer-0 ed
    k_setup<<<SETUP_BW + SETUP_BE + SETUP_BP + SETUP_BED, 256>>>(x_elem, x_proc, W_src);

    const int nblk_gemm = 2 * BLK_E + 2 * BLK_P;

    for (int l = 0; l < 3; l++) {
        k_gemm_es_mma<<<nblk_gemm, 256>>>(att_src + (size_t)l * 4 * D, l);
        k_agg<<<(NTOT * 32 + 255) / 256, 256>>>(bias + (size_t)l * 4 * D, l);
    }

    k_colsum2<<<CSB_E + CSB_P, 128>>>();
    k_finalize<<<1, 32>>>(lin_W, lin_b, out);
}

// round 13
// speedup vs baseline: 1.0463x; 1.0463x over previous
#include <cuda_runtime.h>
#include <cuda_bf16.h>
#include <cuda_fp16.h>
#include <cstdint>

#define NE 50000
#define NP 25000
#define EN 200000
#define D  128
#define NTOT (NE + NP)
#define BINS (2 * NE + 2 * NP)
#define CAP 64
#define BLK_E ((NE + 127) / 128)       // 391
#define BLK_P ((NP + 127) / 128)       // 196

// ---------------- device scratch ----------------
__device__ uint32_t g_hs[(2 * NE + 2 * NP) * (D / 2)];   // half2-packed hs rows
__device__ float g_es[4 * NE];
__device__ float g_edA[NTOT];
__device__ float g_edB[NTOT];
__device__ float g_vd[12 * D];
__device__ float g_colsum[D];
__device__ int   g_deg[BINS];
__device__ int   g_csr_src[BINS * CAP];

// MMA fragment arrays (hi/lo bf16 split), fragment-permuted layout
__device__ uint4 g_xeh[BLK_E * 2048];
__device__ uint4 g_xel[BLK_E * 2048];
__device__ uint4 g_xph[BLK_P * 2048];
__device__ uint4 g_xpl[BLK_P * 2048];
__device__ uint2 g_wh[12 * 16 * 8 * 32];
__device__ uint2 g_wl[12 * 16 * 8 * 32];

struct EPtr { const int* src[4]; const int* dst[4]; };

__device__ __forceinline__ size_t hs_off_u(int t) {
    return (t < 2) ? (size_t)t * NE * (D / 2)
                   : (size_t)2 * NE * (D / 2) + (size_t)(t - 2) * NP * (D / 2);
}
__device__ __forceinline__ int bin_base(int t) {
    const int b[4] = {0, NE, NE + NP, NE + 2 * NP};
    return b[t];
}
__device__ __forceinline__ uint32_t pack_bf16(__nv_bfloat16 a, __nv_bfloat16 b) {
    return (uint32_t)__bfloat16_as_ushort(a) | ((uint32_t)__bfloat16_as_ushort(b) << 16);
}

// ---------------- CSR build + vd (all layers) ----------------
__global__ void k_zero_int(int* p, int n) {
    int i = blockIdx.x * blockDim.x + threadIdx.x;
    if (i < n) p[i] = 0;
}

#define SCAT_B ((4 * EN + 255) / 256)    // 3125
#define VD_B   ((12 * 128 * 32) / 256)   // 192

__global__ void k_scatter(EPtr ep, const float* __restrict__ Wd_all,
                          const float* __restrict__ ad_all) {
    if (blockIdx.x == 0 && threadIdx.x < D) g_colsum[threadIdx.x] = 0.f;
    int b = blockIdx.x;
    int tid = threadIdx.x;
    if (b < SCAT_B) {
        int idx = b * 256 + tid;
        if (idx >= 4 * EN) return;
        int t = idx / EN, e = idx - t * EN;
        int bin = bin_base(t) + ep.dst[t][e];
        int pos = atomicAdd(&g_deg[bin], 1);
        if (pos < CAP) g_csr_src[bin * CAP + pos] = ep.src[t][e];
    } else {
        int gw = ((b - SCAT_B) * 256 + tid) >> 5;
        int lane = tid & 31;
        if (gw >= 12 * 128) return;
        int lt = gw >> 7, r = gw & 127;
        float4 w = ((const float4*)(Wd_all + (size_t)(lt * D + r) * D))[lane];
        float4 a = ((const float4*)(ad_all + (size_t)lt * D))[lane];
        float p = w.x * a.x + w.y * a.y + w.z * a.z + w.w * a.w;
#pragma unroll
        for (int o = 16; o > 0; o >>= 1) p += __shfl_down_sync(0xffffffffu, p, o);
        if (lane == 0) g_vd[lt * D + r] = p;
    }
}

// ---------------- one-time setup ----------------
__device__ __forceinline__ void convert_x_body(const float* __restrict__ x, int M,
                                               uint4* __restrict__ fh, uint4* __restrict__ fl,
                                               int f) {
    int tile = f >> 11, rem = f & 2047;
    int m = rem >> 8, ks = (rem >> 5) & 7, lane = rem & 31;
    int g = lane >> 2, tg = lane & 3;
    int r0 = tile * 128 + m * 16 + g;
    int r1 = r0 + 8;
    int c0 = ks * 16 + tg * 2;
    int c1 = c0 + 8;

    float2 v00 = (r0 < M) ? *(const float2*)(x + (size_t)r0 * D + c0) : make_float2(0.f, 0.f);
    float2 v01 = (r0 < M) ? *(const float2*)(x + (size_t)r0 * D + c1) : make_float2(0.f, 0.f);
    float2 v10 = (r1 < M) ? *(const float2*)(x + (size_t)r1 * D + c0) : make_float2(0.f, 0.f);
    float2 v11 = (r1 < M) ? *(const float2*)(x + (size_t)r1 * D + c1) : make_float2(0.f, 0.f);

    uint4 H, L;
    __nv_bfloat16 h, h2;

    h = __float2bfloat16(v00.x); h2 = __float2bfloat16(v00.y);
    H.x = pack_bf16(h, h2);
    L.x = pack_bf16(__float2bfloat16(v00.x - __bfloat162float(h)),
                    __float2bfloat16(v00.y - __bfloat162float(h2)));
    h = __float2bfloat16(v10.x); h2 = __float2bfloat16(v10.y);
    H.y = pack_bf16(h, h2);
    L.y = pack_bf16(__float2bfloat16(v10.x - __bfloat162float(h)),
                    __float2bfloat16(v10.y - __bfloat162float(h2)));
    h = __float2bfloat16(v01.x); h2 = __float2bfloat16(v01.y);
    H.z = pack_bf16(h, h2);
    L.z = pack_bf16(__float2bfloat16(v01.x - __bfloat162float(h)),
                    __float2bfloat16(v01.y - __bfloat162float(h2)));
    h = __float2bfloat16(v11.x); h2 = __float2bfloat16(v11.y);
    H.w = pack_bf16(h, h2);
    L.w = pack_bf16(__float2bfloat16(v11.x - __bfloat162float(h)),
                    __float2bfloat16(v11.y - __bfloat162float(h2)));

    fh[f] = H;
    fl[f] = L;
}

#define SETUP_BW 192
#define SETUP_BE (BLK_E * 2048 / 256)
#define SETUP_BP (BLK_P * 2048 / 256)
#define SETUP_BED ((NTOT * 32 + 255) / 256)

__global__ void k_setup(const float* __restrict__ xe, const float* __restrict__ xp,
                        const float* __restrict__ Ws_all) {
    int b = blockIdx.x;
    int tid = threadIdx.x;
    if (b < SETUP_BW) {
        int idx = b * 256 + tid;
        int lt = idx >> 12, nb = (idx >> 8) & 15, ks = (idx >> 5) & 7, lane = idx & 31;
        int g = lane >> 2, tg = lane & 3;
        int n = nb * 8 + g;
        int k0 = ks * 16 + tg * 2;
        const float* W = Ws_all + (size_t)lt * D * D;
        float f0 = W[(size_t)k0 * D + n];
        float f1 = W[(size_t)(k0 + 1) * D + n];
        float f2 = W[(size_t)(k0 + 8) * D + n];
        float f3 = W[(size_t)(k0 + 9) * D + n];
        __nv_bfloat16 h0 = __float2bfloat16(f0), h1 = __float2bfloat16(f1);
        __nv_bfloat16 h2 = __float2bfloat16(f2), h3 = __float2bfloat16(f3);
        uint2 H, L;
        H.x = pack_bf16(h0, h1);
        H.y = pack_bf16(h2, h3);
        L.x = pack_bf16(__float2bfloat16(f0 - __bfloat162float(h0)),
                        __float2bfloat16(f1 - __bfloat162float(h1)));
        L.y = pack_bf16(__float2bfloat16(f2 - __bfloat162float(h2)),
                        __float2bfloat16(f3 - __bfloat162float(h3)));
        g_wh[idx] = H;
        g_wl[idx] = L;
    } else if (b < SETUP_BW + SETUP_BE) {
        convert_x_body(xe, NE, g_xeh, g_xel, (b - SETUP_BW) * 256 + tid);
    } else if (b < SETUP_BW + SETUP_BE + SETUP_BP) {
        convert_x_body(xp, NP, g_xph, g_xpl, (b - SETUP_BW - SETUP_BE) * 256 + tid);
    } else {
        int gw = ((b - SETUP_BW - SETUP_BE - SETUP_BP) * 256 + tid) >> 5;
        int lane = tid & 31;
        if (gw >= NTOT) return;
        bool elem = gw < NE;
        int d = elem ? gw : gw - NE;
        const float* x = elem ? xe : xp;
        int tA = elem ? 0 : 1, tB = elem ? 3 : 2;
        float4 xr = ((const float4*)(x + (size_t)d * D))[lane];
        float4 vA = ((const float4*)(g_vd + tA * D))[lane];
        float4 vB = ((const float4*)(g_vd + tB * D))[lane];
        float eA = xr.x * vA.x + xr.y * vA.y + xr.z * vA.z + xr.w * vA.w;
        float eB = xr.x * vB.x + xr.y * vB.y + xr.z * vB.z + xr.w * vB.w;
#pragma unroll
        for (int o = 16; o > 0; o >>= 1) {
            eA += __shfl_xor_sync(0xffffffffu, eA, o);
            eB += __shfl_xor_sync(0xffffffffu, eB, o);
        }
        if (lane == 0) { g_edA[gw] = eA; g_edB[gw] = eB; }
    }
}

// ---------------- split-bf16 MMA GEMM + fused es (R11 layout, distance-2 interleave) ----------------
__device__ __forceinline__ void mma_bf16(float* c, const uint4& a, const uint2& b) {
    asm volatile(
        "mma.sync.aligned.m16n8k16.row.col.f32.bf16.bf16.f32 "
        "{%0,%1,%2,%3}, {%4,%5,%6,%7}, {%8,%9}, {%0,%1,%2,%3};"
        : "+f"(c[0]), "+f"(c[1]), "+f"(c[2]), "+f"(c[3])
        : "r"(a.x), "r"(a.y), "r"(a.z), "r"(a.w), "r"(b.x), "r"(b.y));
}
__device__ __forceinline__ uint32_t f2h2(float a, float b) {
    __half2 h = __floats2half2_rn(a, b);
    return *reinterpret_cast<uint32_t*>(&h);
}

__global__ __launch_bounds__(256, 2) void k_gemm_es_mma(const float* __restrict__ asrc,
                                                        int layer) {
    __shared__ float esb[128];

    int bx = blockIdx.x;
    int t, bb;
    if (bx < BLK_E)                   { t = 0; bb = bx; }
    else if (bx < 2 * BLK_E)          { t = 1; bb = bx - BLK_E; }
    else if (bx < 2 * BLK_E + BLK_P)  { t = 2; bb = bx - 2 * BLK_E; }
    else                              { t = 3; bb = bx - 2 * BLK_E - BLK_P; }

    const uint4* Ah = (t < 2) ? g_xeh : g_xph;
    const uint4* Al = (t < 2) ? g_xel : g_xpl;
    int M          = (t < 2) ? NE : NP;
    uint32_t* C    = g_hs + hs_off_u(t);
    float* es      = g_es + t * NE;
    const float* as_ = asrc + t * D;

    int tid  = threadIdx.x;
    int lane = tid & 31;
    int wid  = tid >> 5;
    int wm   = wid & 3;
    int wn   = wid >> 2;
    int row0 = bb * 128;

    if (tid < 128) esb[tid] = 0.f;
    __syncthreads();

    float acc[2][8][4];
#pragma unroll
    for (int i = 0; i < 2; i++)
#pragma unroll
        for (int j = 0; j < 8; j++)
#pragma unroll
            for (int q = 0; q < 4; q++) acc[i][j][q] = 0.f;

    size_t aBase0 = ((size_t)(bb * 8 + wm * 2 + 0) * 8) * 32 + lane;
    size_t aBase1 = ((size_t)(bb * 8 + wm * 2 + 1) * 8) * 32 + lane;
    size_t bBase  = ((size_t)((layer * 4 + t) * 16 + wn * 8) * 8) * 32 + lane;

#pragma unroll
    for (int ks = 0; ks < 8; ks++) {
        uint4 ah0 = Ah[aBase0 + (size_t)ks * 32];
        uint4 ah1 = Ah[aBase1 + (size_t)ks * 32];
        uint4 al0 = Al[aBase0 + (size_t)ks * 32];
        uint4 al1 = Al[aBase1 + (size_t)ks * 32];
#pragma unroll
        for (int j = 0; j < 8; j++) {
            uint2 bh = g_wh[bBase + ((size_t)j * 8 + ks) * 32];
            uint2 bl = g_wl[bBase + ((size_t)j * 8 + ks) * 32];
            // distance-2 interleave: alternate acc[0]/acc[1], same live set as R11
            mma_bf16(acc[0][j], ah0, bh);
            mma_bf16(acc[1][j], ah1, bh);
            mma_bf16(acc[0][j], ah0, bl);
            mma_bf16(acc[1][j], ah1, bl);
            mma_bf16(acc[0][j], al0, bh);
            mma_bf16(acc[1][j], al1, bh);
        }
    }

    int g = lane >> 2, tg = lane & 3;
#pragma unroll
    for (int i = 0; i < 2; i++) {
        int rbase = row0 + (wm * 2 + i) * 16;
        int ra = rbase + g;
        int rb = rbase + g + 8;
        float ea = 0.f, eb = 0.f;
#pragma unroll
        for (int j = 0; j < 8; j++) {
            int col = (wn * 8 + j) * 8 + tg * 2;
            float a0 = __ldg(as_ + col), a1 = __ldg(as_ + col + 1);
            ea += acc[i][j][0] * a0 + acc[i][j][1] * a1;
            eb += acc[i][j][2] * a0 + acc[i][j][3] * a1;
            if (ra < M) C[(size_t)ra * (D / 2) + (col >> 1)] = f2h2(acc[i][j][0], acc[i][j][1]);
            if (rb < M) C[(size_t)rb * (D / 2) + (col >> 1)] = f2h2(acc[i][j][2], acc[i][j][3]);
        }
        ea += __shfl_xor_sync(0xffffffffu, ea, 1);
        ea += __shfl_xor_sync(0xffffffffu, ea, 2);
        eb += __shfl_xor_sync(0xffffffffu, eb, 1);
        eb += __shfl_xor_sync(0xffffffffu, eb, 2);
        if (tg == 0) {
            atomicAdd(&esb[(wm * 2 + i) * 16 + g], ea);
            atomicAdd(&esb[(wm * 2 + i) * 16 + 8 + g], eb);
        }
    }
    __syncthreads();
    if (tid < 128 && row0 + tid < M) es[row0 + tid] = esb[tid];
}

// ---------------- fused per-dst aggregation + frag conversion / colsum ----------------
__device__ __forceinline__ void gat_accum(int t, int d, float ed, int lane,
                                          float4& acc, float& den) {
    int bin = bin_base(t) + d;
    int deg = g_deg[bin];
    if (deg == 0) return;
    int start = bin * CAP;
    int end = start + deg;

    const float* es_t = g_es + t * NE;
    const uint32_t* hs_t = g_hs + hs_off_u(t);

    int s0 = g_csr_src[start];
    float ev0 = es_t[s0];
    uint2 u0 = ((const uint2*)(hs_t + (size_t)s0 * (D / 2)))[lane];

    for (int e = start; e < end; e++) {
        float ev = ev0;
        uint2 u = u0;
        if (e + 1 < end) {
            int s1 = g_csr_src[e + 1];
            ev0 = es_t[s1];
            u0 = ((const uint2*)(hs_t + (size_t)s1 * (D / 2)))[lane];
        }
        float w = __expf(fmaxf(ev + ed, 0.f));
        den += w;
        float2 f01 = __half22float2(*reinterpret_cast<__half2*>(&u.x));
        float2 f23 = __half22float2(*reinterpret_cast<__half2*>(&u.y));
        acc.x += w * f01.x; acc.y += w * f01.y;
        acc.z += w * f23.x; acc.w += w * f23.y;
    }
}

__global__ __launch_bounds__(256) void k_agg(const float* __restrict__ bias, int layer) {
    __shared__ float csum[128];
    int tid = threadIdx.x;
    int gw = (blockIdx.x * blockDim.x + tid) >> 5;
    int lane = tid & 31;
    bool active = gw < NTOT;

    float4 o = {0.f, 0.f, 0.f, 0.f};
    bool elem = false;
    int d = 0;

    if (active) {
        elem = gw < NE;
        int tA, tB;
        const float *b1, *b2;
        if (elem) { tA = 0; tB = 3; d = gw;       b1 = bias;     b2 = bias + 3 * D; }
        else      { tA = 1; tB = 2; d = gw - NE;  b1 = bias + D; b2 = bias + 2 * D; }

        float edA = g_edA[gw];
        float edB = g_edB[gw];

        float4 accA = {0.f, 0.f, 0.f, 0.f}, accB = {0.f, 0.f, 0.f, 0.f};
        float denA = 0.f, denB = 0.f;
        gat_accum(tA, d, edA, lane, accA, denA);
        gat_accum(tB, d, edB, lane, accB, denB);

        float ia = 1.f / fmaxf(denA, 1e-16f);
        float ib = 1.f / fmaxf(denB, 1e-16f);
        float4 bb1 = ((const float4*)b1)[lane];
        float4 bb2 = ((const float4*)b2)[lane];
        o.x = bb1.x + bb2.x + accA.x * ia + accB.x * ib;
        o.y = bb1.y + bb2.y + accA.y * ia + accB.y * ib;
        o.z = bb1.z + bb2.z + accA.z * ia + accB.z * ib;
        o.w = bb1.w + bb2.w + accA.w * ia + accB.w * ib;
    }

    if (layer == 2) {
        // fused column-sum: block smem reduce, then one global atomic per column
        if (tid < 128) csum[tid] = 0.f;
        __syncthreads();
        if (active) {
            atomicAdd(&csum[lane * 4 + 0], o.x);
            atomicAdd(&csum[lane * 4 + 1], o.y);
            atomicAdd(&csum[lane * 4 + 2], o.z);
            atomicAdd(&csum[lane * 4 + 3], o.w);
        }
        __syncthreads();
        if (tid < 128) atomicAdd(g_colsum + tid, csum[tid]);
        return;
    }

    if (!active) return;

    // fused frag conversion: scatter o into MMA fragment layout
    uint32_t* FH = elem ? (uint32_t*)g_xeh : (uint32_t*)g_xph;
    uint32_t* FL = elem ? (uint32_t*)g_xel : (uint32_t*)g_xpl;
    int tile = d >> 7, w128 = d & 127;
    int m = w128 >> 4, r16 = w128 & 15;
    int gsel = r16 & 7, hsel = r16 >> 3;
    size_t fbase = ((size_t)(tile * 8 + m) * 8) * 32 + gsel * 4;
    float v[4] = {o.x, o.y, o.z, o.w};
#pragma unroll
    for (int pp = 0; pp < 2; pp++) {
        int p = 2 * lane + pp;
        int ks = p >> 3, rem = p & 7;
        int tg = rem & 3, chal = rem >> 2;
        int q = chal * 2 + hsel;
        size_t addr = (fbase + (size_t)ks * 32 + tg) * 4 + q;
        float v0 = v[2 * pp], v1 = v[2 * pp + 1];
        __nv_bfloat16 h0 = __float2bfloat16(v0), h1 = __float2bfloat16(v1);
        FH[addr] = pack_bf16(h0, h1);
        FL[addr] = pack_bf16(__float2bfloat16(v0 - __bfloat162float(h0)),
                             __float2bfloat16(v1 - __bfloat162float(h1)));
    }

    // next-layer ed from o
    int nl = layer + 1;
    int ntA = elem ? 0 : 1, ntB = elem ? 3 : 2;
    float4 vA = ((const float4*)(g_vd + (nl * 4 + ntA) * D))[lane];
    float4 vB = ((const float4*)(g_vd + (nl * 4 + ntB) * D))[lane];
    float eA = o.x * vA.x + o.y * vA.y + o.z * vA.z + o.w * vA.w;
    float eB = o.x * vB.x + o.y * vB.y + o.z * vB.z + o.w * vB.w;
#pragma unroll
    for (int off = 16; off > 0; off >>= 1) {
        eA += __shfl_xor_sync(0xffffffffu, eA, off);
        eB += __shfl_xor_sync(0xffffffffu, eB, off);
    }
    if (lane == 0) { g_edA[gw] = eA; g_edB[gw] = eB; }
}

// ---------------- finalize ----------------
__global__ void k_finalize(const float* __restrict__ lin_W, const float* __restrict__ lin_b,
                           float* __restrict__ out) {
    if (threadIdx.x == 0) {
        float o0 = lin_b[0], o1 = lin_b[1];
        const float inv = 1.f / (float)NTOT;
        for (int i = 0; i < D; i++) {
            float mv = g_colsum[i] * inv;
            o0 += mv * lin_W[2 * i];
            o1 += mv * lin_W[2 * i + 1];
        }
        out[0] = o0;
        out[1] = o1;
    }
}

// ---------------- host orchestration ----------------
extern "C" void kernel_launch(void* const* d_in, const int* in_sizes, int n_in,
                              void* d_out, int out_size) {
    const float* x_elem  = (const float*)d_in[0];
    const float* x_proc  = (const float*)d_in[1];
    const float* W_src   = (const float*)d_in[2];
    const float* W_dst   = (const float*)d_in[3];
    const float* att_src = (const float*)d_in[4];
    const float* att_dst = (const float*)d_in[5];
    const float* bias    = (const float*)d_in[6];
    const float* lin_W   = (const float*)d_in[7];
    const float* lin_b   = (const float*)d_in[8];
    EPtr ep;
    ep.src[0] = (const int*)d_in[9];  ep.dst[0] = (const int*)d_in[10];
    ep.src[1] = (const int*)d_in[11]; ep.dst[1] = (const int*)d_in[12];
    ep.src[2] = (const int*)d_in[13]; ep.dst[2] = (const int*)d_in[14];
    ep.src[3] = (const int*)d_in[15]; ep.dst[3] = (const int*)d_in[16];
    float* out = (float*)d_out;

    int* deg;
    cudaGetSymbolAddress((void**)&deg, g_deg);

    // CSR build + all-layer vd
    k_zero_int<<<(BINS + 255) / 256, 256>>>(deg, BINS);
    k_scatter<<<SCAT_B + VD_B, 256>>>(ep, W_dst, att_dst);

    // one-time: all W frags, input x frags, layer-0 ed
    k_setup<<<SETUP_BW + SETUP_BE + SETUP_BP + SETUP_BED, 256>>>(x_elem, x_proc, W_src);

    const int nblk_gemm = 2 * BLK_E + 2 * BLK_P;

    for (int l = 0; l < 3; l++) {
        k_gemm_es_mma<<<nblk_gemm, 256>>>(att_src + (size_t)l * 4 * D, l);
        k_agg<<<(NTOT * 32 + 255) / 256, 256>>>(bias + (size_t)l * 4 * D, l);
    }

    k_finalize<<<1, 32>>>(lin_W, lin_b, out);
}

// round 14
// speedup vs baseline: 1.1154x; 1.0660x over previous
#include <cuda_runtime.h>
#include <cuda_bf16.h>
#include <cuda_fp16.h>
#include <cstdint>

#define NE 50000
#define NP 25000
#define EN 200000
#define D  128
#define NTOT (NE + NP)
#define BINS (2 * NE + 2 * NP)
#define CAP 64
#define BLK_E ((NE + 127) / 128)       // 391
#define BLK_P ((NP + 127) / 128)       // 196

// ---------------- device scratch ----------------
__device__ uint32_t g_hs[(2 * NE + 2 * NP) * (D / 2)];   // half2-packed hs rows
__device__ float g_es[4 * NE];
__device__ float g_edA[NTOT];
__device__ float g_edB[NTOT];
__device__ float g_vd[12 * D];
__device__ float g_colsum[D];
__device__ int   g_deg[BINS];
__device__ int   g_csr_src[BINS * CAP];

// MMA fragment arrays (hi/lo bf16 split), fragment-permuted layout
__device__ uint4 g_xeh[BLK_E * 2048];
__device__ uint4 g_xel[BLK_E * 2048];
__device__ uint4 g_xph[BLK_P * 2048];
__device__ uint4 g_xpl[BLK_P * 2048];
__device__ uint2 g_wh[12 * 16 * 8 * 32];
__device__ uint2 g_wl[12 * 16 * 8 * 32];

struct EPtr { const int* src[4]; const int* dst[4]; };

__device__ __forceinline__ size_t hs_off_u(int t) {
    return (t < 2) ? (size_t)t * NE * (D / 2)
                   : (size_t)2 * NE * (D / 2) + (size_t)(t - 2) * NP * (D / 2);
}
__device__ __forceinline__ int bin_base(int t) {
    const int b[4] = {0, NE, NE + NP, NE + 2 * NP};
    return b[t];
}
__device__ __forceinline__ uint32_t pack_bf16(__nv_bfloat16 a, __nv_bfloat16 b) {
    return (uint32_t)__bfloat16_as_ushort(a) | ((uint32_t)__bfloat16_as_ushort(b) << 16);
}

// ---------------- CSR build + vd (all layers) ----------------
__global__ void k_zero_int(int* p, int n) {
    int i = blockIdx.x * blockDim.x + threadIdx.x;
    if (i < n) p[i] = 0;
}

#define SCAT_B ((4 * EN + 255) / 256)    // 3125
#define VD_B   ((12 * 128 * 32) / 256)   // 192

__global__ void k_scatter(EPtr ep, const float* __restrict__ Wd_all,
                          const float* __restrict__ ad_all) {
    if (blockIdx.x == 0 && threadIdx.x < D) g_colsum[threadIdx.x] = 0.f;
    int b = blockIdx.x;
    int tid = threadIdx.x;
    if (b < SCAT_B) {
        int idx = b * 256 + tid;
        if (idx >= 4 * EN) return;
        int t = idx / EN, e = idx - t * EN;
        int bin = bin_base(t) + ep.dst[t][e];
        int pos = atomicAdd(&g_deg[bin], 1);
        if (pos < CAP) g_csr_src[bin * CAP + pos] = ep.src[t][e];
    } else {
        int gw = ((b - SCAT_B) * 256 + tid) >> 5;
        int lane = tid & 31;
        if (gw >= 12 * 128) return;
        int lt = gw >> 7, r = gw & 127;
        float4 w = ((const float4*)(Wd_all + (size_t)(lt * D + r) * D))[lane];
        float4 a = ((const float4*)(ad_all + (size_t)lt * D))[lane];
        float p = w.x * a.x + w.y * a.y + w.z * a.z + w.w * a.w;
#pragma unroll
        for (int o = 16; o > 0; o >>= 1) p += __shfl_down_sync(0xffffffffu, p, o);
        if (lane == 0) g_vd[lt * D + r] = p;
    }
}

// ---------------- one-time setup ----------------
__device__ __forceinline__ void convert_x_body(const float* __restrict__ x, int M,
                                               uint4* __restrict__ fh, uint4* __restrict__ fl,
                                               int f) {
    int tile = f >> 11, rem = f & 2047;
    int m = rem >> 8, ks = (rem >> 5) & 7, lane = rem & 31;
    int g = lane >> 2, tg = lane & 3;
    int r0 = tile * 128 + m * 16 + g;
    int r1 = r0 + 8;
    int c0 = ks * 16 + tg * 2;
    int c1 = c0 + 8;

    float2 v00 = (r0 < M) ? *(const float2*)(x + (size_t)r0 * D + c0) : make_float2(0.f, 0.f);
    float2 v01 = (r0 < M) ? *(const float2*)(x + (size_t)r0 * D + c1) : make_float2(0.f, 0.f);
    float2 v10 = (r1 < M) ? *(const float2*)(x + (size_t)r1 * D + c0) : make_float2(0.f, 0.f);
    float2 v11 = (r1 < M) ? *(const float2*)(x + (size_t)r1 * D + c1) : make_float2(0.f, 0.f);

    uint4 H, L;
    __nv_bfloat16 h, h2;

    h = __float2bfloat16(v00.x); h2 = __float2bfloat16(v00.y);
    H.x = pack_bf16(h, h2);
    L.x = pack_bf16(__float2bfloat16(v00.x - __bfloat162float(h)),
                    __float2bfloat16(v00.y - __bfloat162float(h2)));
    h = __float2bfloat16(v10.x); h2 = __float2bfloat16(v10.y);
    H.y = pack_bf16(h, h2);
    L.y = pack_bf16(__float2bfloat16(v10.x - __bfloat162float(h)),
                    __float2bfloat16(v10.y - __bfloat162float(h2)));
    h = __float2bfloat16(v01.x); h2 = __float2bfloat16(v01.y);
    H.z = pack_bf16(h, h2);
    L.z = pack_bf16(__float2bfloat16(v01.x - __bfloat162float(h)),
                    __float2bfloat16(v01.y - __bfloat162float(h2)));
    h = __float2bfloat16(v11.x); h2 = __float2bfloat16(v11.y);
    H.w = pack_bf16(h, h2);
    L.w = pack_bf16(__float2bfloat16(v11.x - __bfloat162float(h)),
                    __float2bfloat16(v11.y - __bfloat162float(h2)));

    fh[f] = H;
    fl[f] = L;
}

#define SETUP_BW 192
#define SETUP_BE (BLK_E * 2048 / 256)
#define SETUP_BP (BLK_P * 2048 / 256)
#define SETUP_BED ((NTOT * 32 + 255) / 256)

__global__ void k_setup(const float* __restrict__ xe, const float* __restrict__ xp,
                        const float* __restrict__ Ws_all) {
    int b = blockIdx.x;
    int tid = threadIdx.x;
    if (b < SETUP_BW) {
        int idx = b * 256 + tid;
        int lt = idx >> 12, nb = (idx >> 8) & 15, ks = (idx >> 5) & 7, lane = idx & 31;
        int g = lane >> 2, tg = lane & 3;
        int n = nb * 8 + g;
        int k0 = ks * 16 + tg * 2;
        const float* W = Ws_all + (size_t)lt * D * D;
        float f0 = W[(size_t)k0 * D + n];
        float f1 = W[(size_t)(k0 + 1) * D + n];
        float f2 = W[(size_t)(k0 + 8) * D + n];
        float f3 = W[(size_t)(k0 + 9) * D + n];
        __nv_bfloat16 h0 = __float2bfloat16(f0), h1 = __float2bfloat16(f1);
        __nv_bfloat16 h2 = __float2bfloat16(f2), h3 = __float2bfloat16(f3);
        uint2 H, L;
        H.x = pack_bf16(h0, h1);
        H.y = pack_bf16(h2, h3);
        L.x = pack_bf16(__float2bfloat16(f0 - __bfloat162float(h0)),
                        __float2bfloat16(f1 - __bfloat162float(h1)));
        L.y = pack_bf16(__float2bfloat16(f2 - __bfloat162float(h2)),
                        __float2bfloat16(f3 - __bfloat162float(h3)));
        g_wh[idx] = H;
        g_wl[idx] = L;
    } else if (b < SETUP_BW + SETUP_BE) {
        convert_x_body(xe, NE, g_xeh, g_xel, (b - SETUP_BW) * 256 + tid);
    } else if (b < SETUP_BW + SETUP_BE + SETUP_BP) {
        convert_x_body(xp, NP, g_xph, g_xpl, (b - SETUP_BW - SETUP_BE) * 256 + tid);
    } else {
        int gw = ((b - SETUP_BW - SETUP_BE - SETUP_BP) * 256 + tid) >> 5;
        int lane = tid & 31;
        if (gw >= NTOT) return;
        bool elem = gw < NE;
        int d = elem ? gw : gw - NE;
        const float* x = elem ? xe : xp;
        int tA = elem ? 0 : 1, tB = elem ? 3 : 2;
        float4 xr = ((const float4*)(x + (size_t)d * D))[lane];
        float4 vA = ((const float4*)(g_vd + tA * D))[lane];
        float4 vB = ((const float4*)(g_vd + tB * D))[lane];
        float eA = xr.x * vA.x + xr.y * vA.y + xr.z * vA.z + xr.w * vA.w;
        float eB = xr.x * vB.x + xr.y * vB.y + xr.z * vB.z + xr.w * vB.w;
#pragma unroll
        for (int o = 16; o > 0; o >>= 1) {
            eA += __shfl_xor_sync(0xffffffffu, eA, o);
            eB += __shfl_xor_sync(0xffffffffu, eB, o);
        }
        if (lane == 0) { g_edA[gw] = eA; g_edB[gw] = eB; }
    }
}

// ---------------- split-bf16 MMA GEMM + fused es (R13 schedule) ----------------
__device__ __forceinline__ void mma_bf16(float* c, const uint4& a, const uint2& b) {
    asm volatile(
        "mma.sync.aligned.m16n8k16.row.col.f32.bf16.bf16.f32 "
        "{%0,%1,%2,%3}, {%4,%5,%6,%7}, {%8,%9}, {%0,%1,%2,%3};"
        : "+f"(c[0]), "+f"(c[1]), "+f"(c[2]), "+f"(c[3])
        : "r"(a.x), "r"(a.y), "r"(a.z), "r"(a.w), "r"(b.x), "r"(b.y));
}
__device__ __forceinline__ uint32_t f2h2(float a, float b) {
    __half2 h = __floats2half2_rn(a, b);
    return *reinterpret_cast<uint32_t*>(&h);
}

__global__ __launch_bounds__(256, 2) void k_gemm_es_mma(const float* __restrict__ asrc,
                                                        int layer) {
    __shared__ float esb[128];

    int bx = blockIdx.x;
    int t, bb;
    if (bx < BLK_E)                   { t = 0; bb = bx; }
    else if (bx < 2 * BLK_E)          { t = 1; bb = bx - BLK_E; }
    else if (bx < 2 * BLK_E + BLK_P)  { t = 2; bb = bx - 2 * BLK_E; }
    else                              { t = 3; bb = bx - 2 * BLK_E - BLK_P; }

    const uint4* Ah = (t < 2) ? g_xeh : g_xph;
    const uint4* Al = (t < 2) ? g_xel : g_xpl;
    int M          = (t < 2) ? NE : NP;
    uint32_t* C    = g_hs + hs_off_u(t);
    float* es      = g_es + t * NE;
    const float* as_ = asrc + t * D;

    int tid  = threadIdx.x;
    int lane = tid & 31;
    int wid  = tid >> 5;
    int wm   = wid & 3;
    int wn   = wid >> 2;
    int row0 = bb * 128;

    if (tid < 128) esb[tid] = 0.f;
    __syncthreads();

    float acc[2][8][4];
#pragma unroll
    for (int i = 0; i < 2; i++)
#pragma unroll
        for (int j = 0; j < 8; j++)
#pragma unroll
            for (int q = 0; q < 4; q++) acc[i][j][q] = 0.f;

    size_t aBase0 = ((size_t)(bb * 8 + wm * 2 + 0) * 8) * 32 + lane;
    size_t aBase1 = ((size_t)(bb * 8 + wm * 2 + 1) * 8) * 32 + lane;
    size_t bBase  = ((size_t)((layer * 4 + t) * 16 + wn * 8) * 8) * 32 + lane;

#pragma unroll
    for (int ks = 0; ks < 8; ks++) {
        uint4 ah0 = Ah[aBase0 + (size_t)ks * 32];
        uint4 ah1 = Ah[aBase1 + (size_t)ks * 32];
        uint4 al0 = Al[aBase0 + (size_t)ks * 32];
        uint4 al1 = Al[aBase1 + (size_t)ks * 32];
#pragma unroll
        for (int j = 0; j < 8; j++) {
            uint2 bh = g_wh[bBase + ((size_t)j * 8 + ks) * 32];
            uint2 bl = g_wl[bBase + ((size_t)j * 8 + ks) * 32];
            mma_bf16(acc[0][j], ah0, bh);
            mma_bf16(acc[1][j], ah1, bh);
            mma_bf16(acc[0][j], ah0, bl);
            mma_bf16(acc[1][j], ah1, bl);
            mma_bf16(acc[0][j], al0, bh);
            mma_bf16(acc[1][j], al1, bh);
        }
    }

    int g = lane >> 2, tg = lane & 3;
#pragma unroll
    for (int i = 0; i < 2; i++) {
        int rbase = row0 + (wm * 2 + i) * 16;
        int ra = rbase + g;
        int rb = rbase + g + 8;
        float ea = 0.f, eb = 0.f;
#pragma unroll
        for (int j = 0; j < 8; j++) {
            int col = (wn * 8 + j) * 8 + tg * 2;
            float a0 = __ldg(as_ + col), a1 = __ldg(as_ + col + 1);
            ea += acc[i][j][0] * a0 + acc[i][j][1] * a1;
            eb += acc[i][j][2] * a0 + acc[i][j][3] * a1;
            if (ra < M) C[(size_t)ra * (D / 2) + (col >> 1)] = f2h2(acc[i][j][0], acc[i][j][1]);
            if (rb < M) C[(size_t)rb * (D / 2) + (col >> 1)] = f2h2(acc[i][j][2], acc[i][j][3]);
        }
        ea += __shfl_xor_sync(0xffffffffu, ea, 1);
        ea += __shfl_xor_sync(0xffffffffu, ea, 2);
        eb += __shfl_xor_sync(0xffffffffu, eb, 1);
        eb += __shfl_xor_sync(0xffffffffu, eb, 2);
        if (tg == 0) {
            atomicAdd(&esb[(wm * 2 + i) * 16 + g], ea);
            atomicAdd(&esb[(wm * 2 + i) * 16 + 8 + g], eb);
        }
    }
    __syncthreads();
    if (tid < 128 && row0 + tid < M) es[row0 + tid] = esb[tid];
}

// ---------------- fused per-dst aggregation, chunk-4 MLP pipeline ----------------
__device__ __forceinline__ void gat_edge(float ev, float ed, const uint2& u,
                                         float4& acc, float& den) {
    float w = __expf(fmaxf(ev + ed, 0.f));
    den += w;
    float2 f01 = __half22float2(*reinterpret_cast<const __half2*>(&u.x));
    float2 f23 = __half22float2(*reinterpret_cast<const __half2*>(&u.y));
    acc.x += w * f01.x; acc.y += w * f01.y;
    acc.z += w * f23.x; acc.w += w * f23.y;
}

__device__ __forceinline__ void gat_accum(int t, int d, float ed, int lane,
                                          float4& acc, float& den) {
    int bin = bin_base(t) + d;
    int deg = g_deg[bin];
    if (deg == 0) return;
    const int start = bin * CAP;

    const float* es_t = g_es + t * NE;
    const uint32_t* hs_t = g_hs + hs_off_u(t);

    int e = 0;
    for (; e + 4 <= deg; e += 4) {
        // 4 independent index loads, then 4 es + 4 row loads all in flight
        int s0 = g_csr_src[start + e + 0];
        int s1 = g_csr_src[start + e + 1];
        int s2 = g_csr_src[start + e + 2];
        int s3 = g_csr_src[start + e + 3];
        float ev0 = es_t[s0], ev1 = es_t[s1], ev2 = es_t[s2], ev3 = es_t[s3];
        uint2 u0 = ((const uint2*)(hs_t + (size_t)s0 * (D / 2)))[lane];
        uint2 u1 = ((const uint2*)(hs_t + (size_t)s1 * (D / 2)))[lane];
        uint2 u2 = ((const uint2*)(hs_t + (size_t)s2 * (D / 2)))[lane];
        uint2 u3 = ((const uint2*)(hs_t + (size_t)s3 * (D / 2)))[lane];
        gat_edge(ev0, ed, u0, acc, den);
        gat_edge(ev1, ed, u1, acc, den);
        gat_edge(ev2, ed, u2, acc, den);
        gat_edge(ev3, ed, u3, acc, den);
    }
    // remainder (0..3 edges), same order
    if (e < deg) {
        int s0 = g_csr_src[start + e];
        int s1 = (e + 1 < deg) ? g_csr_src[start + e + 1] : s0;
        int s2 = (e + 2 < deg) ? g_csr_src[start + e + 2] : s0;
        float ev0 = es_t[s0], ev1 = es_t[s1], ev2 = es_t[s2];
        uint2 u0 = ((const uint2*)(hs_t + (size_t)s0 * (D / 2)))[lane];
        uint2 u1 = ((const uint2*)(hs_t + (size_t)s1 * (D / 2)))[lane];
        uint2 u2 = ((const uint2*)(hs_t + (size_t)s2 * (D / 2)))[lane];
        gat_edge(ev0, ed, u0, acc, den);
        if (e + 1 < deg) gat_edge(ev1, ed, u1, acc, den);
        if (e + 2 < deg) gat_edge(ev2, ed, u2, acc, den);
    }
}

__global__ __launch_bounds__(256) void k_agg(const float* __restrict__ bias, int layer) {
    __shared__ float csum[128];
    int tid = threadIdx.x;
    int gw = (blockIdx.x * blockDim.x + tid) >> 5;
    int lane = tid & 31;
    bool active = gw < NTOT;

    float4 o = {0.f, 0.f, 0.f, 0.f};
    bool elem = false;
    int d = 0;

    if (active) {
        elem = gw < NE;
        int tA, tB;
        const float *b1, *b2;
        if (elem) { tA = 0; tB = 3; d = gw;       b1 = bias;     b2 = bias + 3 * D; }
        else      { tA = 1; tB = 2; d = gw - NE;  b1 = bias + D; b2 = bias + 2 * D; }

        float edA = g_edA[gw];
        float edB = g_edB[gw];

        float4 accA = {0.f, 0.f, 0.f, 0.f}, accB = {0.f, 0.f, 0.f, 0.f};
        float denA = 0.f, denB = 0.f;
        gat_accum(tA, d, edA, lane, accA, denA);
        gat_accum(tB, d, edB, lane, accB, denB);

        float ia = 1.f / fmaxf(denA, 1e-16f);
        float ib = 1.f / fmaxf(denB, 1e-16f);
        float4 bb1 = ((const float4*)b1)[lane];
        float4 bb2 = ((const float4*)b2)[lane];
        o.x = bb1.x + bb2.x + accA.x * ia + accB.x * ib;
        o.y = bb1.y + bb2.y + accA.y * ia + accB.y * ib;
        o.z = bb1.z + bb2.z + accA.z * ia + accB.z * ib;
        o.w = bb1.w + bb2.w + accA.w * ia + accB.w * ib;
    }

    if (layer == 2) {
        if (tid < 128) csum[tid] = 0.f;
        __syncthreads();
        if (active) {
            atomicAdd(&csum[lane * 4 + 0], o.x);
            atomicAdd(&csum[lane * 4 + 1], o.y);
            atomicAdd(&csum[lane * 4 + 2], o.z);
            atomicAdd(&csum[lane * 4 + 3], o.w);
        }
        __syncthreads();
        if (tid < 128) atomicAdd(g_colsum + tid, csum[tid]);
        return;
    }

    if (!active) return;

    // fused frag conversion: scatter o into MMA fragment layout
    uint32_t* FH = elem ? (uint32_t*)g_xeh : (uint32_t*)g_xph;
    uint32_t* FL = elem ? (uint32_t*)g_xel : (uint32_t*)g_xpl;
    int tile = d >> 7, w128 = d & 127;
    int m = w128 >> 4, r16 = w128 & 15;
    int gsel = r16 & 7, hsel = r16 >> 3;
    size_t fbase = ((size_t)(tile * 8 + m) * 8) * 32 + gsel * 4;
    float v[4] = {o.x, o.y, o.z, o.w};
#pragma unroll
    for (int pp = 0; pp < 2; pp++) {
        int p = 2 * lane + pp;
        int ks = p >> 3, rem = p & 7;
        int tg = rem & 3, chal = rem >> 2;
        int q = chal * 2 + hsel;
        size_t addr = (fbase + (size_t)ks * 32 + tg) * 4 + q;
        float v0 = v[2 * pp], v1 = v[2 * pp + 1];
        __nv_bfloat16 h0 = __float2bfloat16(v0), h1 = __float2bfloat16(v1);
        FH[addr] = pack_bf16(h0, h1);
        FL[addr] = pack_bf16(__float2bfloat16(v0 - __bfloat162float(h0)),
                             __float2bfloat16(v1 - __bfloat162float(h1)));
    }

    // next-layer ed from o
    int nl = layer + 1;
    int ntA = elem ? 0 : 1, ntB = elem ? 3 : 2;
    float4 vA = ((const float4*)(g_vd + (nl * 4 + ntA) * D))[lane];
    float4 vB = ((const float4*)(g_vd + (nl * 4 + ntB) * D))[lane];
    float eA = o.x * vA.x + o.y * vA.y + o.z * vA.z + o.w * vA.w;
    float eB = o.x * vB.x + o.y * vB.y + o.z * vB.z + o.w * vB.w;
#pragma unroll
    for (int off = 16; off > 0; off >>= 1) {
        eA += __shfl_xor_sync(0xffffffffu, eA, off);
        eB += __shfl_xor_sync(0xffffffffu, eB, off);
    }
    if (lane == 0) { g_edA[gw] = eA; g_edB[gw] = eB; }
}

// ---------------- finalize ----------------
__global__ void k_finalize(const float* __restrict__ lin_W, const float* __restrict__ lin_b,
                           float* __restrict__ out) {
    if (threadIdx.x == 0) {
        float o0 = lin_b[0], o1 = lin_b[1];
        const float inv = 1.f / (float)NTOT;
        for (int i = 0; i < D; i++) {
            float mv = g_colsum[i] * inv;
            o0 += mv * lin_W[2 * i];
            o1 += mv * lin_W[2 * i + 1];
        }
        out[0] = o0;
        out[1] = o1;
    }
}

// ---------------- host orchestration ----------------
extern "C" void kernel_launch(void* const* d_in, const int* in_sizes, int n_in,
                              void* d_out, int out_size) {
    const float* x_elem  = (const float*)d_in[0];
    const float* x_proc  = (const float*)d_in[1];
    const float* W_src   = (const float*)d_in[2];
    const float* W_dst   = (const float*)d_in[3];
    const float* att_src = (const float*)d_in[4];
    const float* att_dst = (const float*)d_in[5];
    const float* bias    = (const float*)d_in[6];
    const float* lin_W   = (const float*)d_in[7];
    const float* lin_b   = (const float*)d_in[8];
    EPtr ep;
    ep.src[0] = (const int*)d_in[9];  ep.dst[0] = (const int*)d_in[10];
    ep.src[1] = (const int*)d_in[11]; ep.dst[1] = (const int*)d_in[12];
    ep.src[2] = (const int*)d_in[13]; ep.dst[2] = (const int*)d_in[14];
    ep.src[3] = (const int*)d_in[15]; ep.dst[3] = (const int*)d_in[16];
    float* out = (float*)d_out;

    int* deg;
    cudaGetSymbolAddress((void**)&deg, g_deg);

    // CSR build + all-layer vd
    k_zero_int<<<(BINS + 255) / 256, 256>>>(deg, BINS);
    k_scatter<<<SCAT_B + VD_B, 256>>>(ep, W_dst, att_dst);

    // one-time: all W frags, input x frags, layer-0 ed
    k_setup<<<SETUP_BW + SETUP_BE + SETUP_BP + SETUP_BED, 256>>>(x_elem, x_proc, W_src);

    const int nblk_gemm = 2 * BLK_E + 2 * BLK_P;

    for (int l = 0; l < 3; l++) {
        k_gemm_es_mma<<<nblk_gemm, 256>>>(att_src + (size_t)l * 4 * D, l);
        k_agg<<<(NTOT * 32 + 255) / 256, 256>>>(bias + (size_t)l * 4 * D, l);
    }

    k_finalize<<<1, 32>>>(lin_W, lin_b, out);
}